// round 2
// baseline (speedup 1.0000x reference)
#include <cuda_runtime.h>
#include <math.h>

// Problem constants (fixed shapes from reference setup_inputs)
#define N_ROWS 256
#define N_EMB  16384
#define DIMK   2048
#define KNN_   6
#define N_NEI  (N_ROWS * KNN_)   // 1536
#define INV_BETA 20.0f

// ---------------- scratch (device globals; no allocation allowed) ----------------
__device__ float g_L[(size_t)N_ROWS * N_EMB];   // 16 MB logits
__device__ int   g_tidx[N_NEI];                 // top-6 indices per row (flattened)
__device__ float g_tval[N_NEI];                 // top-6 logit values
__device__ float g_lse[N_ROWS];
__device__ float g_tlog[N_ROWS];                // logit at target
__device__ float g_thr[N_NEI];                  // S[row, anchor] threshold
__device__ int   g_anc[N_NEI];                  // anchor index per neighbor row
__device__ int   g_cnt[N_NEI];                  // count of sims preceding anchor
__device__ int   g_tgt[N_ROWS];                 // normalized int32 targets

// ---------------- targets dtype normalization ----------------
// Reference declares int64, but JAX default (x64 disabled) coerces to int32.
// Detect: if buffer is int64 (values in [0,16384)), odd int32 words are 0.
// First 256 bytes are in-bounds for either dtype (256 elems >= 64 int32 words).
__global__ void load_targets_kernel(const int* __restrict__ t32)
{
    __shared__ int is64;
    if (threadIdx.x == 0) {
        int z = 1;
        #pragma unroll
        for (int i = 1; i < 64; i += 2)
            if (t32[i] != 0) z = 0;
        is64 = z;
    }
    __syncthreads();
    int m = threadIdx.x;           // exactly 256 threads
    g_tgt[m] = is64 ? t32[2 * m] : t32[m];
}

// ---------------- tiled SGEMM (NT: both operands K-contiguous) ----------------
// BM=BN=128, BK=16, 256 threads, 8x8 per thread (split 4+4 for conflict-free LDS.128)
#define BM 128
#define BN 128
#define BKD 16

template<bool GATHER_A, bool COUNT>
__global__ __launch_bounds__(256, 2)
void gemm_kernel(const float* __restrict__ A, const float* __restrict__ B, float scale)
{
    __shared__ float As[BKD][BM];
    __shared__ float Bs[BKD][BN];

    const int bm  = blockIdx.y * BM;
    const int bn  = blockIdx.x * BN;
    const int tid = threadIdx.x;
    const int tr  = tid >> 4;        // 0..15
    const int tc  = tid & 15;        // 0..15

    // Resolve global row pointers once (A may be gathered via g_tidx)
    const float* arowptr[2];
    const float* browptr[2];
    {
        int r0 = tid >> 2;           // 0..63
        #pragma unroll
        for (int i = 0; i < 2; i++) {
            int gr  = bm + r0 + i * 64;
            int src = GATHER_A ? g_tidx[gr] : gr;
            arowptr[i] = A + (size_t)src * DIMK;
            browptr[i] = B + (size_t)(bn + r0 + i * 64) * DIMK;
        }
    }
    const int kq = (tid & 3) * 4;    // k offset 0/4/8/12
    const int r0 = tid >> 2;

    float acc[8][8];
    #pragma unroll
    for (int i = 0; i < 8; i++)
        #pragma unroll
        for (int j = 0; j < 8; j++) acc[i][j] = 0.f;

    for (int k0 = 0; k0 < DIMK; k0 += BKD) {
        #pragma unroll
        for (int i = 0; i < 2; i++) {
            int row = r0 + i * 64;
            float4 v = *(const float4*)(arowptr[i] + k0 + kq);
            As[kq + 0][row] = v.x; As[kq + 1][row] = v.y;
            As[kq + 2][row] = v.z; As[kq + 3][row] = v.w;
            float4 w = *(const float4*)(browptr[i] + k0 + kq);
            Bs[kq + 0][row] = w.x; Bs[kq + 1][row] = w.y;
            Bs[kq + 2][row] = w.z; Bs[kq + 3][row] = w.w;
        }
        __syncthreads();
        #pragma unroll
        for (int kk = 0; kk < BKD; kk++) {
            float4 a0 = *(const float4*)&As[kk][tr * 4];
            float4 a1 = *(const float4*)&As[kk][64 + tr * 4];
            float4 b0 = *(const float4*)&Bs[kk][tc * 4];
            float4 b1 = *(const float4*)&Bs[kk][64 + tc * 4];
            float ar[8] = {a0.x, a0.y, a0.z, a0.w, a1.x, a1.y, a1.z, a1.w};
            float br[8] = {b0.x, b0.y, b0.z, b0.w, b1.x, b1.y, b1.z, b1.w};
            #pragma unroll
            for (int i = 0; i < 8; i++)
                #pragma unroll
                for (int j = 0; j < 8; j++)
                    acc[i][j] = fmaf(ar[i], br[j], acc[i][j]);
        }
        __syncthreads();
    }

    if (!COUNT) {
        // write scaled logits: rows R(i)=tr*4+(i&3)+(i>>2)*64, cols C(j)=tc*4+(j&3)+(j>>2)*64
        #pragma unroll
        for (int i = 0; i < 8; i++) {
            int gr = bm + tr * 4 + (i & 3) + ((i >> 2) * 64);
            float* crow = g_L + (size_t)gr * N_EMB + bn;
            float4 v0 = make_float4(acc[i][0] * scale, acc[i][1] * scale,
                                    acc[i][2] * scale, acc[i][3] * scale);
            float4 v1 = make_float4(acc[i][4] * scale, acc[i][5] * scale,
                                    acc[i][6] * scale, acc[i][7] * scale);
            *(float4*)(crow + tc * 4)      = v0;
            *(float4*)(crow + 64 + tc * 4) = v1;
        }
    } else {
        // count epilogue: elements preceding anchor in descending (val, idx) order
        __shared__ int scnt[BM];
        for (int i = tid; i < BM; i += 256) scnt[i] = 0;
        __syncthreads();
        #pragma unroll
        for (int i = 0; i < 8; i++) {
            int lr = tr * 4 + (i & 3) + ((i >> 2) * 64);
            int gr = bm + lr;
            float t = g_thr[gr];
            int   a = g_anc[gr];
            int   c = 0;
            #pragma unroll
            for (int j = 0; j < 8; j++) {
                int col = bn + tc * 4 + (j & 3) + ((j >> 2) * 64);
                float s = acc[i][j];
                if (col != a && (s > t || (s == t && col < a))) c++;
            }
            if (c) atomicAdd(&scnt[lr], c);
        }
        __syncthreads();
        for (int i = tid; i < BM; i += 256) {
            int v = scnt[i];
            if (v) atomicAdd(&g_cnt[bm + i], v);
        }
    }
}

// ---------------- per-row: top-6 + logsumexp + target logit ----------------
__global__ __launch_bounds__(256)
void row_reduce_kernel()
{
    const int m   = blockIdx.x;
    const int tid = threadIdx.x;
    const float* row = g_L + (size_t)m * N_EMB;

    float bv[KNN_]; int bi[KNN_];
    #pragma unroll
    for (int k = 0; k < KNN_; k++) { bv[k] = -3.0e38f; bi[k] = 0x7fffffff; }
    float worst = -3.0e38f;
    float mx = -3.0e38f, sum = 0.f;

    for (int j = tid; j < N_EMB; j += 256) {
        float v = row[j];
        if (v > mx) { sum = sum * __expf(mx - v) + 1.f; mx = v; }
        else        { sum += __expf(v - mx); }
        if (v > worst) {   // strictly greater: equal keeps earlier index (matches top_k)
            int p = KNN_ - 1;
            while (p > 0 && (v > bv[p - 1])) { bv[p] = bv[p - 1]; bi[p] = bi[p - 1]; p--; }
            bv[p] = v; bi[p] = j;
            worst = bv[KNN_ - 1];
        }
    }

    __shared__ float sv[256 * KNN_];
    __shared__ int   si[256 * KNN_];
    __shared__ float rv[256];
    __shared__ int   ri[256];
    __shared__ int   rt[256];
    __shared__ float smx[256];
    __shared__ float ssum[256];

    #pragma unroll
    for (int k = 0; k < KNN_; k++) { sv[tid * KNN_ + k] = bv[k]; si[tid * KNN_ + k] = bi[k]; }
    smx[tid] = mx; ssum[tid] = sum;
    __syncthreads();

    // LSE tree reduce
    for (int s = 128; s > 0; s >>= 1) {
        if (tid < s) {
            float m1 = smx[tid], m2 = smx[tid + s];
            float M  = fmaxf(m1, m2);
            ssum[tid] = ssum[tid] * __expf(m1 - M) + ssum[tid + s] * __expf(m2 - M);
            smx[tid]  = M;
        }
        __syncthreads();
    }
    if (tid == 0) {
        g_lse[m]  = smx[0] + logf(ssum[0]);
        g_tlog[m] = row[g_tgt[m]];
    }

    // merge 256 sorted 6-lists -> global top-6 (value desc, index asc)
    int head = 0;
    for (int round = 0; round < KNN_; round++) {
        float mv; int mi;
        if (head < KNN_) { mv = sv[tid * KNN_ + head]; mi = si[tid * KNN_ + head]; }
        else             { mv = -3.0e38f; mi = 0x7fffffff; }
        rv[tid] = mv; ri[tid] = mi; rt[tid] = tid;
        __syncthreads();
        for (int s = 128; s > 0; s >>= 1) {
            if (tid < s) {
                float v2 = rv[tid + s]; int i2 = ri[tid + s];
                if (v2 > rv[tid] || (v2 == rv[tid] && i2 < ri[tid])) {
                    rv[tid] = v2; ri[tid] = i2; rt[tid] = rt[tid + s];
                }
            }
            __syncthreads();
        }
        if (tid == 0) { g_tval[m * KNN_ + round] = rv[0]; g_tidx[m * KNN_ + round] = ri[0]; }
        int w = rt[0];
        __syncthreads();        // everyone has read rt[0] before next round overwrites
        if (tid == w) head++;
    }
}

// ---------------- thresholds: S[r, anchor] = em[t_r] . em[anchor_m] ----------------
__global__ __launch_bounds__(256)
void thr_kernel(const float* __restrict__ em)
{
    const int r = blockIdx.x;
    const int m = r / KNN_;
    const int t = g_tidx[r];
    const int a = g_tidx[m * KNN_];   // top-1 logit index = anchor
    const float* x = em + (size_t)t * DIMK;
    const float* y = em + (size_t)a * DIMK;
    float s = 0.f;
    for (int j = threadIdx.x * 4; j < DIMK; j += 256 * 4) {
        float4 xv = *(const float4*)(x + j);
        float4 yv = *(const float4*)(y + j);
        s += xv.x * yv.x + xv.y * yv.y + xv.z * yv.z + xv.w * yv.w;
    }
    __shared__ float red[256];
    red[threadIdx.x] = s;
    __syncthreads();
    for (int sft = 128; sft > 0; sft >>= 1) {
        if (threadIdx.x < sft) red[threadIdx.x] += red[threadIdx.x + sft];
        __syncthreads();
    }
    if (threadIdx.x == 0) { g_thr[r] = red[0]; g_anc[r] = a; g_cnt[r] = 0; }
}

// ---------------- final losses ----------------
__global__ __launch_bounds__(256)
void finalize_kernel(float* __restrict__ out)
{
    const int m = threadIdx.x;    // one thread per batch row, exactly 256
    float l  = g_lse[m];
    float lt = g_tlog[m];
    int  tgt = g_tgt[m];
    float p_t = expf(lt - l);
    float P_rec = 0.f, extra = 0.f;
    #pragma unroll
    for (int k = 0; k < KNN_; k++) {
        int idx = g_tidx[m * KNN_ + k];
        if (idx != tgt && g_cnt[m * KNN_ + k] <= 5) {   // recip & not overwritten by target
            float v = g_tval[m * KNN_ + k];
            P_rec += expf(v - l);
            extra += 0.5f * (v - l);
        }
    }
    float beta = -((lt - l) + extra);
    const float LOG_HALF = -0.6931471805599453f;
    const float LOG_EPS  = -9.210340371976182f;   // log(1e-4)
    float alpha = -(P_rec * LOG_HALF + (1.f - p_t - P_rec) * LOG_EPS);

    __shared__ float sa[256], sb[256];
    sa[m] = alpha; sb[m] = beta;
    __syncthreads();
    for (int s = 128; s > 0; s >>= 1) {
        if (m < s) { sa[m] += sa[m + s]; sb[m] += sb[m + s]; }
        __syncthreads();
    }
    if (m == 0) {
        out[0] = 0.05f * (sa[0] / 256.f);   // UL_ALPHA * alpha_loss
        out[1] = sb[0] / 256.f;             // UL_BETA  * beta_loss
    }
}

// ---------------- launch ----------------
extern "C" void kernel_launch(void* const* d_in, const int* in_sizes, int n_in,
                              void* d_out, int out_size)
{
    const float* inputs  = (const float*)d_in[0];
    const float* em      = (const float*)d_in[1];
    const int*   targets = (const int*)d_in[2];   // width auto-detected in kernel
    float* out = (float*)d_out;
    (void)in_sizes; (void)n_in; (void)out_size;

    // 0) normalize targets (int32 vs int64)
    load_targets_kernel<<<1, 256>>>(targets);
    // 1) logits = inputs @ em.T * 20
    gemm_kernel<false, false><<<dim3(N_EMB / BN, N_ROWS / BM), 256>>>(inputs, em, INV_BETA);
    // 2) per-row top-6 + LSE + target logit
    row_reduce_kernel<<<N_ROWS, 256>>>();
    // 3) anchor-sim thresholds (+ zero counts)
    thr_kernel<<<N_NEI, 256>>>(em);
    // 4) sims GEMM with fused count-above-threshold epilogue
    gemm_kernel<true, true><<<dim3(N_EMB / BN, N_NEI / BM), 256>>>(em, em, 1.0f);
    // 5) losses
    finalize_kernel<<<1, 256>>>(out);
}